// round 1
// baseline (speedup 1.0000x reference)
#include <cuda_runtime.h>
#include <math.h>
#include <stdint.h>

#define CC   512
#define NN1  8192
#define NN2  131072
#define NTOT 139265
#define EE   1000000
#define KK1  820
#define KK2  3280
#define MM   4101

// output layout (float32, tuple concatenated)
#define OFF_XPOOL 0ULL
#define OFF_A     2099712ULL
#define OFF_BATCH 18917913ULL
#define OFF_CLUST 18922014ULL
#define OFF_NNT   19061279ULL
#define OFF_NTREE 19065380ULL
#define OFF_FIT   19069481ULL
#define OFF_NEWXY 19208746ULL

// ---------------- device scratch ----------------
__device__ float g_f1[NN1];
__device__ float g_f2[NN2];
__device__ float g_thr[KK1 * 3];          // threshold xyf
__device__ int   g_cluster1[NN1];
__device__ int   g_parents[NN2];
__device__ int   g_counts1[KK1];
__device__ int   g_starts1[KK1];
__device__ int   g_offs1[KK1];
__device__ int   g_gmembers[NN2];
__device__ int   g_cand_idx[KK1 * 4];
__device__ float g_cand_xyf[KK1 * 4 * 3];
__device__ int   g_cluster[NTOT];
__device__ int   g_countsM[MM];
__device__ int   g_startsM[MM];
__device__ int   g_offsM[MM];
__device__ int   g_cmembers[NTOT];
__device__ int   g_minTree;
__device__ float g_norm1, g_norm2;

__device__ __forceinline__ unsigned int f2ord(float f) {
    unsigned int u = __float_as_uint(f);
    return (u & 0x80000000u) ? ~u : (u | 0x80000000u);
}

// ---------------- kernels ----------------
__global__ void init_kernel() {
    int i = blockIdx.x * blockDim.x + threadIdx.x;
    if (i < KK1) { g_counts1[i] = 0; g_offs1[i] = 0; }
    if (i < MM)  { g_countsM[i] = 0; g_offsM[i] = 0; }
    if (i == 0)  { g_minTree = 0x7fffffff; g_cluster[0] = 0; }
}

__global__ void norm_kernel(const float* __restrict__ w1, const float* __restrict__ w2) {
    __shared__ float s1[512], s2[512];
    int t = threadIdx.x;
    s1[t] = w1[t] * w1[t];
    s2[t] = w2[t] * w2[t];
    __syncthreads();
    for (int off = 256; off; off >>= 1) {
        if (t < off) { s1[t] += s1[t + off]; s2[t] += s2[t + off]; }
        __syncthreads();
    }
    if (t == 0) { g_norm1 = sqrtf(s1[0]); g_norm2 = sqrtf(s2[0]); }
}

// one warp per row: f = tanh(dot(x_row, w)/||w||)
__global__ void f_kernel(const float* __restrict__ x,
                         const float* __restrict__ w1,
                         const float* __restrict__ w2) {
    int gw = (blockIdx.x * blockDim.x + threadIdx.x) >> 5;
    int lane = threadIdx.x & 31;
    if (gw >= NN1 + NN2) return;
    const float4* xr = (const float4*)(x + (size_t)(1 + gw) * CC);
    const float4* wr = (const float4*)((gw < NN1) ? w1 : w2);
    float s = 0.f;
#pragma unroll
    for (int k = 0; k < 4; k++) {
        float4 a = xr[lane + 32 * k];
        float4 b = wr[lane + 32 * k];
        s += a.x * b.x; s += a.y * b.y; s += a.z * b.z; s += a.w * b.w;
    }
    for (int off = 16; off; off >>= 1) s += __shfl_xor_sync(0xffffffffu, s, off);
    if (lane == 0) {
        float nrm = (gw < NN1) ? g_norm1 : g_norm2;
        float f = tanhf(s / nrm);
        if (gw < NN1) g_f1[gw] = f; else g_f2[gw - NN1] = f;
    }
}

__global__ void mintree_kernel(const int* __restrict__ tree) {
    __shared__ int sm[256];
    int v = 0x7fffffff;
    for (int i = blockIdx.x * blockDim.x + threadIdx.x; i < NN2; i += gridDim.x * blockDim.x)
        v = min(v, tree[1 + NN1 + i]);
    sm[threadIdx.x] = v;
    __syncthreads();
    for (int off = 128; off; off >>= 1) {
        if (threadIdx.x < off) sm[threadIdx.x] = min(sm[threadIdx.x], sm[threadIdx.x + off]);
        __syncthreads();
    }
    if (threadIdx.x == 0) atomicMin(&g_minTree, sm[0]);
}

// single-block bitonic sort of (f1, idx) composite u64 keys; emit thresholds
__global__ void sort_f1_kernel(const float* __restrict__ xy) {
    extern __shared__ unsigned long long s[];
    int t = threadIdx.x;
    for (int k = t; k < NN1; k += 1024)
        s[k] = ((unsigned long long)f2ord(g_f1[k]) << 32) | (unsigned)k;
    __syncthreads();
    for (int size = 2; size <= NN1; size <<= 1) {
        for (int stride = size >> 1; stride > 0; stride >>= 1) {
            for (int i = t; i < NN1; i += 1024) {
                int j = i ^ stride;
                if (j > i) {
                    unsigned long long a = s[i], b = s[j];
                    bool asc = ((i & size) == 0);
                    if ((a > b) == asc) { s[i] = b; s[j] = a; }
                }
            }
            __syncthreads();
        }
    }
    for (int k = t; k < KK1; k += 1024) {
        int idx = (int)(unsigned)(s[k * 10] & 0xffffffffULL);
        g_thr[k * 3 + 0] = xy[(size_t)(1 + idx) * 2];
        g_thr[k * 3 + 1] = xy[(size_t)(1 + idx) * 2 + 1];
        g_thr[k * 3 + 2] = g_f1[idx];
    }
}

// cluster_1: nearest threshold (first-min tie break)
__global__ void cluster1_kernel(const float* __restrict__ xy) {
    __shared__ float sx[KK1], sy[KK1], sf[KK1];
    for (int k = threadIdx.x; k < KK1; k += blockDim.x) {
        sx[k] = g_thr[k * 3 + 0];
        sy[k] = g_thr[k * 3 + 1];
        sf[k] = g_thr[k * 3 + 2];
    }
    __syncthreads();
    int j = blockIdx.x * blockDim.x + threadIdx.x;
    if (j >= NN1) return;
    float xj = xy[(size_t)(1 + j) * 2];
    float yj = xy[(size_t)(1 + j) * 2 + 1];
    float fj = g_f1[j];
    float best = INFINITY;
    int bi = 0;
    for (int tk = 0; tk < KK1; tk++) {
        float dx = sx[tk] - xj, dy = sy[tk] - yj;
        float d = sqrtf(dx * dx + dy * dy) + fabsf(sf[tk] - fj);
        if (d < best) { best = d; bi = tk; }
    }
    g_cluster1[j] = bi;
    g_cluster[1 + j] = bi + 1;
}

__global__ void parents_kernel(const int* __restrict__ tree) {
    int i = blockIdx.x * blockDim.x + threadIdx.x;
    if (i >= NN2) return;
    int p = g_cluster1[tree[1 + NN1 + i] - g_minTree];
    g_parents[i] = p;
    atomicAdd(&g_counts1[p], 1);
}

// single-block exclusive scan, n <= 8192. which=0: counts1->starts1 (KK1); which=1: countsM->startsM (MM)
__global__ void scan_excl_kernel(int which) {
    __shared__ int ts[1024];
    const int* in = which ? g_countsM : g_counts1;
    int* out = which ? g_startsM : g_starts1;
    int n = which ? MM : KK1;
    int t = threadIdx.x;
    int PER = (n + 1023) >> 10;
    int base = t * PER;
    int loc[8];
    int s = 0;
    for (int i = 0; i < PER; i++) {
        int v = (base + i < n) ? in[base + i] : 0;
        loc[i] = s; s += v;
    }
    ts[t] = s;
    __syncthreads();
    for (int off = 1; off < 1024; off <<= 1) {
        int a = (t >= off) ? ts[t - off] : 0;
        __syncthreads();
        ts[t] += a;
        __syncthreads();
    }
    int prev = (t > 0) ? ts[t - 1] : 0;
    for (int i = 0; i < PER; i++)
        if (base + i < n) out[base + i] = prev + loc[i];
}

__global__ void scatter1_kernel() {
    int i = blockIdx.x * blockDim.x + threadIdx.x;
    if (i >= NN2) return;
    int p = g_parents[i];
    int pos = g_starts1[p] + atomicAdd(&g_offs1[p], 1);
    g_gmembers[pos] = i;
}

// warp-per-group top-4 smallest (comp_key, idx); reproduces stable argsort of 4p+f2
__global__ void top4_kernel(const float* __restrict__ xy) {
    int g = (blockIdx.x * blockDim.x + threadIdx.x) >> 5;
    int lane = threadIdx.x & 31;
    if (g >= KK1) return;
    int start = g_starts1[g], cnt = g_counts1[g];
    const unsigned long long SENT = 0xFFFFFFFFFFFFFFFFull;
    unsigned long long best[4] = {SENT, SENT, SENT, SENT};
    float p4 = 4.0f * (float)g;
    for (int k = lane; k < cnt; k += 32) {
        int i = g_gmembers[start + k];
        float key = p4 + g_f2[i];
        unsigned long long v = ((unsigned long long)f2ord(key) << 32) | (unsigned)i;
        if (v < best[3]) {
            if (v < best[0]) { best[3]=best[2]; best[2]=best[1]; best[1]=best[0]; best[0]=v; }
            else if (v < best[1]) { best[3]=best[2]; best[2]=best[1]; best[1]=v; }
            else if (v < best[2]) { best[3]=best[2]; best[2]=v; }
            else best[3]=v;
        }
    }
    int ptr = 0;
    for (int r = 0; r < 4; r++) {
        unsigned long long v = (ptr < 4) ? best[ptr] : SENT;
        unsigned long long m = v;
        for (int off = 16; off; off >>= 1) {
            unsigned long long o = __shfl_xor_sync(0xffffffffu, m, off);
            if (o < m) m = o;
        }
        unsigned ball = __ballot_sync(0xffffffffu, (ptr < 4) && (v == m));
        if (ball) { int src = __ffs(ball) - 1; if (lane == src) ptr++; }
        if (lane == 0) {
            bool valid = (m != SENT);
            int idx = valid ? (int)(unsigned)(m & 0xffffffffULL) : -1;
            g_cand_idx[g * 4 + r] = idx;
            if (valid) {
                g_cand_xyf[(g * 4 + r) * 3 + 0] = xy[(size_t)(1 + NN1 + idx) * 2];
                g_cand_xyf[(g * 4 + r) * 3 + 1] = xy[(size_t)(1 + NN1 + idx) * 2 + 1];
                g_cand_xyf[(g * 4 + r) * 3 + 2] = g_f2[idx];
            }
        }
    }
}

__global__ void cluster2_kernel(const float* __restrict__ xy) {
    int i = blockIdx.x * blockDim.x + threadIdx.x;
    if (i >= NN2) return;
    int p = g_parents[i];
    float xi = xy[(size_t)(1 + NN1 + i) * 2];
    float yi = xy[(size_t)(1 + NN1 + i) * 2 + 1];
    float fi = g_f2[i];
    float best = INFINITY;
    int loc = 0;
#pragma unroll
    for (int r = 0; r < 4; r++) {
        int ci = g_cand_idx[p * 4 + r];
        if (ci >= 0) {
            float ax = g_cand_xyf[(p * 4 + r) * 3 + 0];
            float ay = g_cand_xyf[(p * 4 + r) * 3 + 1];
            float af = g_cand_xyf[(p * 4 + r) * 3 + 2];
            float dx = ax - xi, dy = ay - yi;
            float d = sqrtf(dx * dx + dy * dy) + fabsf(af - fi);
            if (d < best) { best = d; loc = r; }
        }
    }
    g_cluster[1 + NN1 + i] = p * 4 + loc + 1 + KK1;
}

__global__ void countM_kernel() {
    int i = blockIdx.x * blockDim.x + threadIdx.x;
    if (i >= NTOT) return;
    atomicAdd(&g_countsM[g_cluster[i]], 1);
}

__global__ void scatterM_kernel() {
    int i = blockIdx.x * blockDim.x + threadIdx.x;
    if (i >= NTOT) return;
    int c = g_cluster[i];
    int pos = g_startsM[c] + atomicAdd(&g_offsM[c], 1);
    g_cmembers[pos] = i;
}

// one block per output cluster; 512 threads = one per channel
__global__ void pool_kernel(const float* __restrict__ x, float* __restrict__ out) {
    int m = blockIdx.x;
    int t = threadIdx.x;
    int start = g_startsM[m];
    int cnt = g_countsM[m];
    float acc = 0.f;
    int k = 0;
    for (; k + 4 <= cnt; k += 4) {
        int n0 = g_cmembers[start + k];
        int n1 = g_cmembers[start + k + 1];
        int n2 = g_cmembers[start + k + 2];
        int n3 = g_cmembers[start + k + 3];
        float a0 = x[(size_t)n0 * CC + t];
        float a1 = x[(size_t)n1 * CC + t];
        float a2 = x[(size_t)n2 * CC + t];
        float a3 = x[(size_t)n3 * CC + t];
        acc += a0 + a1 + a2 + a3;
    }
    for (; k < cnt; k++) {
        int n0 = g_cmembers[start + k];
        acc += x[(size_t)n0 * CC + t];
    }
    out[OFF_XPOOL + (size_t)m * CC + t] = acc / (float)(cnt > 0 ? cnt : 1);
}

// one warp per cluster: mean x_y_index
__global__ void xy_kernel(const float* __restrict__ xy, float* __restrict__ out) {
    int gw = (blockIdx.x * blockDim.x + threadIdx.x) >> 5;
    int lane = threadIdx.x & 31;
    if (gw >= MM) return;
    int start = g_startsM[gw], cnt = g_countsM[gw];
    float ax = 0.f, ay = 0.f;
    for (int k = lane; k < cnt; k += 32) {
        int node = g_cmembers[start + k];
        ax += xy[(size_t)node * 2];
        ay += xy[(size_t)node * 2 + 1];
    }
    for (int off = 16; off; off >>= 1) {
        ax += __shfl_xor_sync(0xffffffffu, ax, off);
        ay += __shfl_xor_sync(0xffffffffu, ay, off);
    }
    if (lane == 0) {
        float c = (float)(cnt > 0 ? cnt : 1);
        out[OFF_NEWXY + (size_t)gw * 2]     = ax / c;
        out[OFF_NEWXY + (size_t)gw * 2 + 1] = ay / c;
    }
}

__global__ void zeroA_kernel(float* __restrict__ out) {
    size_t n = (size_t)MM * MM;
    for (size_t i = (size_t)blockIdx.x * blockDim.x + threadIdx.x; i < n;
         i += (size_t)gridDim.x * blockDim.x)
        out[OFF_A + i] = 0.f;
}

__global__ void edge_kernel(const int* __restrict__ ei, float* __restrict__ out) {
    for (int e = blockIdx.x * blockDim.x + threadIdx.x; e < EE; e += gridDim.x * blockDim.x) {
        int r = g_cluster[ei[e]];
        int c = g_cluster[ei[EE + e]];
        atomicAdd(&out[OFF_A + (size_t)r * MM + c], 1.0f);
    }
}

__global__ void tail_kernel(float* __restrict__ out) {
    for (int i = blockIdx.x * blockDim.x + threadIdx.x; i < NTOT; i += gridDim.x * blockDim.x) {
        out[OFF_CLUST + i] = (float)g_cluster[i];
        float fit;
        if (i == 0) fit = 0.f;
        else if (i <= NN1) fit = g_f1[i - 1];
        else fit = g_f2[i - 1 - NN1];
        out[OFF_FIT + i] = fit;
        if (i < MM) {
            out[OFF_BATCH + i] = 0.f;
            out[OFF_NNT + i] = (i == 0) ? 0.f : ((i <= KK1) ? 1.f : 2.f);
            out[OFF_NTREE + i] = (i == 0) ? -1.f : ((i <= KK1) ? 0.f : (float)((i - 1 - KK1) / 4 + 1));
            // self-loop diagonal contribution: one atomic per cluster row
            atomicAdd(&out[OFF_A + (size_t)i * MM + i], (float)g_countsM[i]);
        }
    }
}

// ---------------- launch ----------------
extern "C" void kernel_launch(void* const* d_in, const int* in_sizes, int n_in,
                              void* d_out, int out_size) {
    const float* x    = (const float*)d_in[0];
    const int*   ei   = (const int*)d_in[1];
    const int*   tree = (const int*)d_in[3];
    const float* xy   = (const float*)d_in[4];
    const float* w1   = (const float*)d_in[5];
    const float* w2   = (const float*)d_in[6];
    float* out = (float*)d_out;

    cudaFuncSetAttribute(sort_f1_kernel, cudaFuncAttributeMaxDynamicSharedMemorySize, 65536);

    init_kernel<<<(MM + 255) / 256, 256>>>();
    norm_kernel<<<1, 512>>>(w1, w2);
    f_kernel<<<((NN1 + NN2) * 32 + 255) / 256, 256>>>(x, w1, w2);
    mintree_kernel<<<64, 256>>>(tree);
    sort_f1_kernel<<<1, 1024, 65536>>>(xy);
    cluster1_kernel<<<(NN1 + 255) / 256, 256>>>(xy);
    parents_kernel<<<(NN2 + 255) / 256, 256>>>(tree);
    scan_excl_kernel<<<1, 1024>>>(0);
    scatter1_kernel<<<(NN2 + 255) / 256, 256>>>();
    top4_kernel<<<(KK1 * 32 + 255) / 256, 256>>>(xy);
    cluster2_kernel<<<(NN2 + 255) / 256, 256>>>(xy);
    countM_kernel<<<(NTOT + 255) / 256, 256>>>();
    scan_excl_kernel<<<1, 1024>>>(1);
    scatterM_kernel<<<(NTOT + 255) / 256, 256>>>();
    pool_kernel<<<MM, 512>>>(x, out);
    xy_kernel<<<(MM * 32 + 255) / 256, 256>>>(xy, out);
    zeroA_kernel<<<4096, 256>>>(out);
    edge_kernel<<<2048, 256>>>(ei, out);
    tail_kernel<<<(NTOT + 255) / 256, 256>>>(out);
}

// round 2
// speedup vs baseline: 1.4702x; 1.4702x over previous
#include <cuda_runtime.h>
#include <math.h>
#include <stdint.h>

#define CC   512
#define NN1  8192
#define NN2  131072
#define NTOT 139265
#define EE   1000000
#define KK1  820
#define KK2  3280
#define MM   4101

// output layout (float32, tuple concatenated)
#define OFF_XPOOL 0ULL
#define OFF_A     2099712ULL
#define OFF_BATCH 18917913ULL
#define OFF_CLUST 18922014ULL
#define OFF_NNT   19061279ULL
#define OFF_NTREE 19065380ULL
#define OFF_FIT   19069481ULL
#define OFF_NEWXY 19208746ULL

// ---------------- device scratch ----------------
__device__ float g_f1[NN1];
__device__ float g_f2[NN2];
__device__ int   g_rank[NN1];
__device__ float g_thr[KK1 * 3];
__device__ int   g_cluster1[NN1];
__device__ int   g_parents[NN2];
__device__ int   g_counts1[KK1];
__device__ int   g_starts1[KK1];
__device__ int   g_offs1[KK1];
__device__ int   g_gmembers[NN2];
__device__ int   g_cand_idx[KK1 * 4];
__device__ float g_cand_xyf[KK1 * 4 * 3];
__device__ int   g_cluster[NTOT];
__device__ int   g_countsM[MM];
__device__ int   g_startsM[MM];
__device__ int   g_offsM[MM];
__device__ int   g_cmembers[NTOT];
__device__ int   g_minTree;
__device__ float g_norm1, g_norm2;

__device__ __forceinline__ unsigned int f2ord(float f) {
    unsigned int u = __float_as_uint(f);
    return (u & 0x80000000u) ? ~u : (u | 0x80000000u);
}

// ---------------- setup: zero counters, norms, minTree init, node-0 bookkeeping
__global__ void setup_kernel(const float* __restrict__ w1, const float* __restrict__ w2) {
    int i = blockIdx.x * blockDim.x + threadIdx.x;  // 8192 threads
    if (i < NN1) g_rank[i] = 0;
    if (i < KK1) { g_counts1[i] = 0; g_offs1[i] = 0; }
    if (i < MM)  { g_countsM[i] = (i == 0) ? 1 : 0; g_offsM[i] = 0; }
    if (i == 0)  { g_minTree = 0x7fffffff; g_cluster[0] = 0; }
    if (blockIdx.x == 0) {
        __shared__ float s1[256], s2[256];
        int t = threadIdx.x;
        float a = w1[t], b = w1[t + 256];
        float c = w2[t], d = w2[t + 256];
        s1[t] = a * a + b * b;
        s2[t] = c * c + d * d;
        __syncthreads();
        for (int off = 128; off; off >>= 1) {
            if (t < off) { s1[t] += s1[t + off]; s2[t] += s2[t + off]; }
            __syncthreads();
        }
        if (t == 0) { g_norm1 = sqrtf(s1[0]); g_norm2 = sqrtf(s2[0]); }
    }
}

// one warp per row: f = tanh(dot(x_row, w)/||w||); blocks 0..63 also do tree-min
__global__ void f_kernel(const float* __restrict__ x,
                         const float* __restrict__ w1,
                         const float* __restrict__ w2,
                         const int* __restrict__ tree) {
    if (blockIdx.x < 64) {
        __shared__ int smin[256];
        int v = 0x7fffffff;
        for (int i = blockIdx.x * 256 + threadIdx.x; i < NN2; i += 64 * 256)
            v = min(v, tree[1 + NN1 + i]);
        smin[threadIdx.x] = v;
        __syncthreads();
        for (int off = 128; off; off >>= 1) {
            if (threadIdx.x < off) smin[threadIdx.x] = min(smin[threadIdx.x], smin[threadIdx.x + off]);
            __syncthreads();
        }
        if (threadIdx.x == 0) atomicMin(&g_minTree, smin[0]);
        __syncthreads();
    }
    int gw = (blockIdx.x * blockDim.x + threadIdx.x) >> 5;
    int lane = threadIdx.x & 31;
    if (gw >= NN1 + NN2) return;
    const float4* xr = (const float4*)(x + (size_t)(1 + gw) * CC);
    const float4* wr = (const float4*)((gw < NN1) ? w1 : w2);
    float s = 0.f;
#pragma unroll
    for (int k = 0; k < 4; k++) {
        float4 a = xr[lane + 32 * k];
        float4 b = wr[lane + 32 * k];
        s += a.x * b.x; s += a.y * b.y; s += a.z * b.z; s += a.w * b.w;
    }
    for (int off = 16; off; off >>= 1) s += __shfl_xor_sync(0xffffffffu, s, off);
    if (lane == 0) {
        float nrm = (gw < NN1) ? g_norm1 : g_norm2;
        float f = tanhf(s / nrm);
        if (gw < NN1) g_f1[gw] = f; else g_f2[gw - NN1] = f;
    }
}

// brute-force stable rank of f1 (composite u64 keys), 32 i-chunks x 8 j-chunks
__global__ void rank_kernel() {
    __shared__ unsigned long long sk[1024];
    int jbase = (blockIdx.x & 7) * 1024;
    int i = (blockIdx.x >> 3) * 256 + threadIdx.x;
    for (int k = threadIdx.x; k < 1024; k += 256) {
        int j = jbase + k;
        sk[k] = ((unsigned long long)f2ord(g_f1[j]) << 32) | (unsigned)j;
    }
    __syncthreads();
    unsigned long long ki = ((unsigned long long)f2ord(g_f1[i]) << 32) | (unsigned)i;
    int c = 0;
#pragma unroll 8
    for (int k = 0; k < 1024; k++) c += (sk[k] < ki) ? 1 : 0;
    atomicAdd(&g_rank[i], c);
}

// every element with rank % 10 == 0 is a threshold at slot rank/10
__global__ void thr_kernel(const float* __restrict__ xy) {
    int i = blockIdx.x * blockDim.x + threadIdx.x;
    if (i >= NN1) return;
    int r = g_rank[i];
    if (r % 10 == 0) {
        int s = r / 10;
        g_thr[s * 3 + 0] = xy[(size_t)(1 + i) * 2];
        g_thr[s * 3 + 1] = xy[(size_t)(1 + i) * 2 + 1];
        g_thr[s * 3 + 2] = g_f1[i];
    }
}

// cluster_1: warp per node, lexicographic (d, t) first-min; fused countsM
__global__ void cluster1_kernel(const float* __restrict__ xy) {
    __shared__ float sx[KK1], sy[KK1], sf[KK1];
    for (int k = threadIdx.x; k < KK1; k += blockDim.x) {
        sx[k] = g_thr[k * 3 + 0];
        sy[k] = g_thr[k * 3 + 1];
        sf[k] = g_thr[k * 3 + 2];
    }
    __syncthreads();
    int node = blockIdx.x * 8 + (threadIdx.x >> 5);
    int lane = threadIdx.x & 31;
    if (node >= NN1) return;
    float xj = xy[(size_t)(1 + node) * 2];
    float yj = xy[(size_t)(1 + node) * 2 + 1];
    float fj = g_f1[node];
    float best = INFINITY;
    int bt = KK1;
    for (int t = lane; t < KK1; t += 32) {
        float dx = sx[t] - xj, dy = sy[t] - yj;
        float d = sqrtf(dx * dx + dy * dy) + fabsf(sf[t] - fj);
        if (d < best) { best = d; bt = t; }
    }
    for (int off = 16; off; off >>= 1) {
        float ob = __shfl_xor_sync(0xffffffffu, best, off);
        int   ot = __shfl_xor_sync(0xffffffffu, bt, off);
        if (ob < best || (ob == best && ot < bt)) { best = ob; bt = ot; }
    }
    if (lane == 0) {
        g_cluster1[node] = bt;
        g_cluster[1 + node] = bt + 1;
        atomicAdd(&g_countsM[bt + 1], 1);
    }
}

__global__ void parents_kernel(const int* __restrict__ tree) {
    int i = blockIdx.x * blockDim.x + threadIdx.x;
    if (i >= NN2) return;
    int p = g_cluster1[tree[1 + NN1 + i] - g_minTree];
    g_parents[i] = p;
    atomicAdd(&g_counts1[p], 1);
}

// single-block exclusive scan, n <= 8192
__global__ void scan_excl_kernel(int which) {
    __shared__ int ts[1024];
    const int* in = which ? g_countsM : g_counts1;
    int* out = which ? g_startsM : g_starts1;
    int n = which ? MM : KK1;
    int t = threadIdx.x;
    int PER = (n + 1023) >> 10;
    int base = t * PER;
    int loc[8];
    int s = 0;
    for (int i = 0; i < PER; i++) {
        int v = (base + i < n) ? in[base + i] : 0;
        loc[i] = s; s += v;
    }
    ts[t] = s;
    __syncthreads();
    for (int off = 1; off < 1024; off <<= 1) {
        int a = (t >= off) ? ts[t - off] : 0;
        __syncthreads();
        ts[t] += a;
        __syncthreads();
    }
    int prev = (t > 0) ? ts[t - 1] : 0;
    for (int i = 0; i < PER; i++)
        if (base + i < n) out[base + i] = prev + loc[i];
}

__global__ void scatter1_kernel() {
    int i = blockIdx.x * blockDim.x + threadIdx.x;
    if (i >= NN2) return;
    int p = g_parents[i];
    int pos = g_starts1[p] + atomicAdd(&g_offs1[p], 1);
    g_gmembers[pos] = i;
}

// warp-per-group top-4 smallest (comp_key, idx); stable
__global__ void top4_kernel(const float* __restrict__ xy) {
    int g = (blockIdx.x * blockDim.x + threadIdx.x) >> 5;
    int lane = threadIdx.x & 31;
    if (g >= KK1) return;
    int start = g_starts1[g], cnt = g_counts1[g];
    const unsigned long long SENT = 0xFFFFFFFFFFFFFFFFull;
    unsigned long long best[4] = {SENT, SENT, SENT, SENT};
    float p4 = 4.0f * (float)g;
    for (int k = lane; k < cnt; k += 32) {
        int i = g_gmembers[start + k];
        float key = p4 + g_f2[i];
        unsigned long long v = ((unsigned long long)f2ord(key) << 32) | (unsigned)i;
        if (v < best[3]) {
            if (v < best[0]) { best[3]=best[2]; best[2]=best[1]; best[1]=best[0]; best[0]=v; }
            else if (v < best[1]) { best[3]=best[2]; best[2]=best[1]; best[1]=v; }
            else if (v < best[2]) { best[3]=best[2]; best[2]=v; }
            else best[3]=v;
        }
    }
    int ptr = 0;
    for (int r = 0; r < 4; r++) {
        unsigned long long v = (ptr < 4) ? best[ptr] : SENT;
        unsigned long long m = v;
        for (int off = 16; off; off >>= 1) {
            unsigned long long o = __shfl_xor_sync(0xffffffffu, m, off);
            if (o < m) m = o;
        }
        unsigned ball = __ballot_sync(0xffffffffu, (ptr < 4) && (v == m));
        if (ball) { int src = __ffs(ball) - 1; if (lane == src) ptr++; }
        if (lane == 0) {
            bool valid = (m != SENT);
            int idx = valid ? (int)(unsigned)(m & 0xffffffffULL) : -1;
            g_cand_idx[g * 4 + r] = idx;
            if (valid) {
                g_cand_xyf[(g * 4 + r) * 3 + 0] = xy[(size_t)(1 + NN1 + idx) * 2];
                g_cand_xyf[(g * 4 + r) * 3 + 1] = xy[(size_t)(1 + NN1 + idx) * 2 + 1];
                g_cand_xyf[(g * 4 + r) * 3 + 2] = g_f2[idx];
            }
        }
    }
}

// cluster_2 + fused countsM
__global__ void cluster2_kernel(const float* __restrict__ xy) {
    int i = blockIdx.x * blockDim.x + threadIdx.x;
    if (i >= NN2) return;
    int p = g_parents[i];
    float xi = xy[(size_t)(1 + NN1 + i) * 2];
    float yi = xy[(size_t)(1 + NN1 + i) * 2 + 1];
    float fi = g_f2[i];
    float best = INFINITY;
    int loc = 0;
#pragma unroll
    for (int r = 0; r < 4; r++) {
        int ci = g_cand_idx[p * 4 + r];
        if (ci >= 0) {
            float ax = g_cand_xyf[(p * 4 + r) * 3 + 0];
            float ay = g_cand_xyf[(p * 4 + r) * 3 + 1];
            float af = g_cand_xyf[(p * 4 + r) * 3 + 2];
            float dx = ax - xi, dy = ay - yi;
            float d = sqrtf(dx * dx + dy * dy) + fabsf(af - fi);
            if (d < best) { best = d; loc = r; }
        }
    }
    int c = p * 4 + loc + 1 + KK1;
    g_cluster[1 + NN1 + i] = c;
    atomicAdd(&g_countsM[c], 1);
}

__global__ void scatterM_kernel() {
    int i = blockIdx.x * blockDim.x + threadIdx.x;
    if (i >= NTOT) return;
    int c = g_cluster[i];
    int pos = g_startsM[c] + atomicAdd(&g_offsM[c], 1);
    g_cmembers[pos] = i;
}

// one block per output cluster; 512 threads = one per channel; warp 0 also does xy mean
__global__ void pool_kernel(const float* __restrict__ x, const float* __restrict__ xy,
                            float* __restrict__ out) {
    int m = blockIdx.x;
    int t = threadIdx.x;
    int start = g_startsM[m];
    int cnt = g_countsM[m];
    float acc = 0.f;
    int k = 0;
    for (; k + 4 <= cnt; k += 4) {
        int n0 = g_cmembers[start + k];
        int n1 = g_cmembers[start + k + 1];
        int n2 = g_cmembers[start + k + 2];
        int n3 = g_cmembers[start + k + 3];
        float a0 = x[(size_t)n0 * CC + t];
        float a1 = x[(size_t)n1 * CC + t];
        float a2 = x[(size_t)n2 * CC + t];
        float a3 = x[(size_t)n3 * CC + t];
        acc += a0 + a1 + a2 + a3;
    }
    for (; k < cnt; k++) {
        int n0 = g_cmembers[start + k];
        acc += x[(size_t)n0 * CC + t];
    }
    float inv = 1.0f / (float)(cnt > 0 ? cnt : 1);
    out[OFF_XPOOL + (size_t)m * CC + t] = acc * inv;
    if (t < 32) {
        float ax = 0.f, ay = 0.f;
        for (int kk = t; kk < cnt; kk += 32) {
            int node = g_cmembers[start + kk];
            ax += xy[(size_t)node * 2];
            ay += xy[(size_t)node * 2 + 1];
        }
        for (int off = 16; off; off >>= 1) {
            ax += __shfl_xor_sync(0xffffffffu, ax, off);
            ay += __shfl_xor_sync(0xffffffffu, ay, off);
        }
        if (t == 0) {
            out[OFF_NEWXY + (size_t)m * 2]     = ax * inv;
            out[OFF_NEWXY + (size_t)m * 2 + 1] = ay * inv;
        }
    }
}

__global__ void edge_kernel(const int* __restrict__ ei, float* __restrict__ out) {
    for (int e = blockIdx.x * blockDim.x + threadIdx.x; e < EE; e += gridDim.x * blockDim.x) {
        int r = g_cluster[ei[e]];
        int c = g_cluster[ei[EE + e]];
        atomicAdd(&out[OFF_A + (size_t)r * MM + c], 1.0f);
    }
}

__global__ void tail_kernel(float* __restrict__ out) {
    for (int i = blockIdx.x * blockDim.x + threadIdx.x; i < NTOT; i += gridDim.x * blockDim.x) {
        out[OFF_CLUST + i] = (float)g_cluster[i];
        float fit;
        if (i == 0) fit = 0.f;
        else if (i <= NN1) fit = g_f1[i - 1];
        else fit = g_f2[i - 1 - NN1];
        out[OFF_FIT + i] = fit;
        if (i < MM) {
            out[OFF_BATCH + i] = 0.f;
            out[OFF_NNT + i] = (i == 0) ? 0.f : ((i <= KK1) ? 1.f : 2.f);
            out[OFF_NTREE + i] = (i == 0) ? -1.f : ((i <= KK1) ? 0.f : (float)((i - 1 - KK1) / 4 + 1));
            atomicAdd(&out[OFF_A + (size_t)i * MM + i], (float)g_countsM[i]);
        }
    }
}

// ---------------- launch ----------------
extern "C" void kernel_launch(void* const* d_in, const int* in_sizes, int n_in,
                              void* d_out, int out_size) {
    const float* x    = (const float*)d_in[0];
    const int*   ei   = (const int*)d_in[1];
    const int*   tree = (const int*)d_in[3];
    const float* xy   = (const float*)d_in[4];
    const float* w1   = (const float*)d_in[5];
    const float* w2   = (const float*)d_in[6];
    float* out = (float*)d_out;

    cudaMemsetAsync(out + OFF_A, 0, (size_t)MM * MM * sizeof(float), 0);
    setup_kernel<<<32, 256>>>(w1, w2);
    f_kernel<<<((NN1 + NN2) * 32 + 255) / 256, 256>>>(x, w1, w2, tree);
    rank_kernel<<<256, 256>>>();
    thr_kernel<<<32, 256>>>(xy);
    cluster1_kernel<<<NN1 / 8, 256>>>(xy);
    parents_kernel<<<(NN2 + 255) / 256, 256>>>(tree);
    scan_excl_kernel<<<1, 1024>>>(0);
    scatter1_kernel<<<(NN2 + 255) / 256, 256>>>();
    top4_kernel<<<(KK1 * 32 + 255) / 256, 256>>>(xy);
    cluster2_kernel<<<(NN2 + 255) / 256, 256>>>(xy);
    scan_excl_kernel<<<1, 1024>>>(1);
    scatterM_kernel<<<(NTOT + 255) / 256, 256>>>();
    pool_kernel<<<MM, 512>>>(x, xy, out);
    edge_kernel<<<2048, 256>>>(ei, out);
    tail_kernel<<<(NTOT + 255) / 256, 256>>>(out);
}